// round 13
// baseline (speedup 1.0000x reference)
#include <cuda_runtime.h>
#include <cuda_fp16.h>
#include <cstdint>

#define NP 76832          // 32 * 49 * 49 patches
#define HN 49
#define SLEN 104
#define MROWS_PAD 76928   // 601 * 128 (also divisible by 64 -> 1202 tiles)

// conv output scratch, fp16, layout [patch][pix*20 + oc] (zero-init; pad rows zero)
__device__ __half g_h2[(size_t)MROWS_PAD * 1280];
// pre-converted fp16 weights
__device__ __align__(16) __half g_fc1h[256 * 1280];   // K permuted to pix*20+oc
__device__ __align__(16) __half g_fc2h[256 * 256];
__device__ __align__(16) __half g_fc3h[256 * 256];
__device__ __align__(16) __half g_fcfh[32 * 264];     // zero-padded
__device__ __align__(16) __half g_w2h[3 * 24 * 80];   // [dy][oc][dx*24+ic], zero-pad
__device__ __align__(16) __half g_w1h[3 * 24 * 32];   // [dy][oc][dx*8+ic], zero-pad

// ---------------------------------------------------------------------------
__device__ __forceinline__ uint32_t s2u(const void* p) {
    return (uint32_t)__cvta_generic_to_shared(p);
}
__device__ __forceinline__ void ldsm4(uint32_t* r, uint32_t addr) {
    asm volatile("ldmatrix.sync.aligned.m8n8.x4.shared.b16 {%0,%1,%2,%3}, [%4];"
        : "=r"(r[0]), "=r"(r[1]), "=r"(r[2]), "=r"(r[3]) : "r"(addr));
}
__device__ __forceinline__ void ldsm2(uint32_t* r, uint32_t addr) {
    asm volatile("ldmatrix.sync.aligned.m8n8.x2.shared.b16 {%0,%1}, [%2];"
        : "=r"(r[0]), "=r"(r[1]) : "r"(addr));
}
__device__ __forceinline__ void mma_f16(float* c, const uint32_t* a,
                                        uint32_t b0, uint32_t b1) {
    asm volatile(
        "mma.sync.aligned.m16n8k16.row.col.f32.f16.f16.f32 "
        "{%0,%1,%2,%3}, {%4,%5,%6,%7}, {%8,%9}, {%0,%1,%2,%3};"
        : "+f"(c[0]), "+f"(c[1]), "+f"(c[2]), "+f"(c[3])
        : "r"(a[0]), "r"(a[1]), "r"(a[2]), "r"(a[3]), "r"(b0), "r"(b1));
}
__device__ __forceinline__ uint32_t pack_h2(float a, float b) {
    __half2 h = __floats2half2_rn(a, b);
    return *(uint32_t*)&h;
}
__device__ __forceinline__ void cp16(uint32_t dst, const void* src) {
    asm volatile("cp.async.ca.shared.global [%0], [%1], 16;"
        :: "r"(dst), "l"(src));
}
#define CP_COMMIT() asm volatile("cp.async.commit_group;" ::: "memory")
#define CP_WAIT0()  asm volatile("cp.async.wait_group 0;" ::: "memory")
#define CP_WAIT1()  asm volatile("cp.async.wait_group 1;" ::: "memory")

// ===========================================================================
// Kernel 0: one-shot fp16 weight conversion / re-layout
// ===========================================================================
__global__ __launch_bounds__(256) void convert_kernel(
    const float* __restrict__ fc1_w, const float* __restrict__ fc2_w,
    const float* __restrict__ fc3_w, const float* __restrict__ fcf_w,
    const float* __restrict__ w2, const float* __restrict__ w1)
{
    const int i = blockIdx.x * 256 + threadIdx.x;
    if (i < 256 * 1280) {
        int n = i / 1280, k = i % 1280;
        int oc = k / 64, pix = k % 64;
        g_fc1h[(size_t)n * 1280 + pix * 20 + oc] = __float2half(fc1_w[i]);
    }
    if (i < 256 * 256) {
        g_fc2h[i] = __float2half(fc2_w[i]);
        g_fc3h[i] = __float2half(fc3_w[i]);
    }
    if (i < 32 * 264) {
        int r = i / 264, k = i % 264;
        g_fcfh[i] = (r < 27 && k < 256) ? __float2half(fcf_w[r * 256 + k])
                                        : __half(0.f);
    }
    if (i < 3 * 24 * 80) {
        int dy = i / 1920, r = i % 1920, oc = r / 80, k = r % 80;
        int dx = k / 24, ic = k % 24;
        g_w2h[i] = (oc < 20 && k < 72 && ic < 20)
                 ? __float2half(w2[oc * 180 + ic * 9 + dy * 3 + dx]) : __half(0.f);
    }
    if (i < 3 * 24 * 32) {
        int dy = i / 768, r = i % 768, oc = r / 32, k = r % 32;
        int dx = k / 8, ic = k % 8;
        g_w1h[i] = (oc < 20 && dx < 3 && ic < 2)
                 ? __float2half(w1[oc * 18 + ic * 9 + dy * 3 + dx]) : __half(0.f);
    }
}

// ===========================================================================
// Kernel 1: conv1 + conv2, both fp16 mma with dx-packed K (unchanged from R10)
// ===========================================================================
#define CV_H1   0
#define CV_W2   19232
#define CV_INH  30752
#define CV_W1H  37152
#define CV_B1   41760
#define CV_B2   41856
#define CV_SMEM 41952

__global__ __launch_bounds__(256) void conv_mma_kernel(
    const float* __restrict__ images,
    const float* __restrict__ b1, const float* __restrict__ b2)
{
    extern __shared__ __align__(16) char smc[];
    __half* sH1  = (__half*)(smc + CV_H1);
    __half* sW2  = (__half*)(smc + CV_W2);
    __half* sInH = (__half*)(smc + CV_INH);
    __half* sW1h = (__half*)(smc + CV_W1H);
    float*  sB1  = (float*)(smc + CV_B1);
    float*  sB2  = (float*)(smc + CV_B2);

    const int tid = threadIdx.x;

    {
        uint32_t* z = (uint32_t*)smc;
        for (int i = tid; i < 19232 / 4; i += 256) z[i] = 0u;
        uint32_t* z2 = (uint32_t*)(smc + CV_INH);
        for (int i = tid; i < 6400 / 4; i += 256) z2[i] = 0u;
    }
    for (int i = tid; i < 720; i += 256)
        ((uint4*)sW2)[i] = ((const uint4*)g_w2h)[i];
    for (int i = tid; i < 288; i += 256)
        ((uint4*)sW1h)[i] = ((const uint4*)g_w1h)[i];
    if (tid < 24) {
        sB1[tid] = (tid < 20) ? b1[tid] : 0.f;
        sB2[tid] = (tid < 20) ? b2[tid] : 0.f;
    }

    const int lp  = tid >> 6;
    const int pix = tid & 63;
    const int y = pix >> 3, x = pix & 7;
    const int patch = blockIdx.x * 4 + lp;
    const int b  = patch / (HN * HN);
    const int t2 = patch % (HN * HN);
    const int i0 = (t2 / HN) * 2, j0 = (t2 % HN) * 2;
    __syncthreads();

    {
        const float c0 = images[((size_t)(b * 2 + 0) * SLEN + (i0 + y)) * SLEN + (j0 + x)];
        const float c1 = images[((size_t)(b * 2 + 1) * SLEN + (i0 + y)) * SLEN + (j0 + x)];
        const int rr = (y + 1) * 10 + (x + 1);
        *(uint32_t*)&sInH[lp * 800 + rr * 8] = pack_h2(c0, c1);
    }
    __syncthreads();

    const int l    = tid & 31;
    const int wid  = tid >> 5;
    const int lp_w = wid >> 1;
    const int hf   = wid & 1;
    const int g    = l >> 2;
    const int tig  = l & 3;
    const int l16  = l & 15, lg = l >> 4;

    const int pA0 = hf * 32 + l16;
    const int pA1 = pA0 + 16;
    const int rT0 = (pA0 >> 3) * 10 + (pA0 & 7);
    const int rT1 = (pA1 >> 3) * 10 + (pA1 & 7);

    const int bt   = l >> 3;
    const int bn01 = (bt >> 1) * 8 + (l & 7);
    const int bk01 = (bt & 1) * 8;
    const int l2   = l & 15;
    const int bn2  = 16 + (l2 & 7);
    const int bk2  = ((l2 >> 3) & 1) * 8;

    // ---- conv1 ----
    {
        const uint32_t sInU = s2u(sInH + lp_w * 800);
        const uint32_t sW1u = s2u(sW1h);
        const uint32_t aI0 = sInU + (uint32_t)(rT0 * 8 + lg * 8) * 2;
        const uint32_t aI1 = sInU + (uint32_t)(rT1 * 8 + lg * 8) * 2;
        const uint32_t bW10 = sW1u + (uint32_t)(bn01 * 32 + bk01) * 2;
        const uint32_t bW12 = sW1u + (uint32_t)(bn2 * 32 + bk2) * 2;

        float acc1[2][3][4];
        #pragma unroll
        for (int mt = 0; mt < 2; mt++)
            #pragma unroll
            for (int nt = 0; nt < 3; nt++)
                #pragma unroll
                for (int q = 0; q < 4; q++) acc1[mt][nt][q] = 0.f;

        #pragma unroll
        for (int dy = 0; dy < 3; dy++) {
            const uint32_t ro = (uint32_t)dy * 160;
            const uint32_t wo = (uint32_t)dy * 1536;
            #pragma unroll
            for (int c = 0; c < 2; c++) {
                const uint32_t ko = (uint32_t)c * 32;
                uint32_t a0[4], a1[4], b01[4], bb2[2];
                ldsm4(a0, aI0 + ro + ko);
                ldsm4(a1, aI1 + ro + ko);
                ldsm4(b01, bW10 + wo + ko);
                ldsm2(bb2, bW12 + wo + ko);
                mma_f16(acc1[0][0], a0, b01[0], b01[1]);
                mma_f16(acc1[0][1], a0, b01[2], b01[3]);
                mma_f16(acc1[0][2], a0, bb2[0], bb2[1]);
                mma_f16(acc1[1][0], a1, b01[0], b01[1]);
                mma_f16(acc1[1][1], a1, b01[2], b01[3]);
                mma_f16(acc1[1][2], a1, bb2[0], bb2[1]);
            }
        }

        __half* h1w = sH1 + lp_w * 2400;
        #pragma unroll
        for (int mt = 0; mt < 2; mt++) {
            const int row = hf * 32 + mt * 16 + g;
            const int rc0 = ((row >> 3) + 1) * 10 + (row & 7) + 1;
            const int rc1 = (((row + 8) >> 3) + 1) * 10 + (row & 7) + 1;
            #pragma unroll
            for (int nt = 0; nt < 3; nt++) {
                const int col = nt * 8 + tig * 2;
                if (col < 20) {
                    const float v0 = sB1[col], v1 = sB1[col + 1];
                    *(uint32_t*)&h1w[rc0 * 24 + col] =
                        pack_h2(fmaxf(acc1[mt][nt][0] + v0, 0.f),
                                fmaxf(acc1[mt][nt][1] + v1, 0.f));
                    *(uint32_t*)&h1w[rc1 * 24 + col] =
                        pack_h2(fmaxf(acc1[mt][nt][2] + v0, 0.f),
                                fmaxf(acc1[mt][nt][3] + v1, 0.f));
                }
            }
        }
    }
    __syncthreads();

    // ---- conv2 ----
    const uint32_t sH1u = s2u(sH1 + lp_w * 2400);
    const uint32_t sW2u = s2u(sW2);
    const uint32_t aB0 = sH1u + (uint32_t)(rT0 * 24 + lg * 8) * 2;
    const uint32_t aB1 = sH1u + (uint32_t)(rT1 * 24 + lg * 8) * 2;
    const uint32_t bB01 = sW2u + (uint32_t)(bn01 * 80 + bk01) * 2;
    const uint32_t bB2  = sW2u + (uint32_t)(bn2 * 80 + bk2) * 2;

    float acc[2][3][4];
    #pragma unroll
    for (int mt = 0; mt < 2; mt++)
        #pragma unroll
        for (int nt = 0; nt < 3; nt++)
            #pragma unroll
            for (int q = 0; q < 4; q++) acc[mt][nt][q] = 0.f;

    #pragma unroll
    for (int dy = 0; dy < 3; dy++) {
        const uint32_t ro = (uint32_t)dy * 480;
        const uint32_t wo = (uint32_t)dy * 3840;
        #pragma unroll
        for (int c = 0; c < 5; c++) {
            const uint32_t ko = (uint32_t)c * 32;
            uint32_t a0[4], a1[4], b01[4], bb2[2];
            ldsm4(a0, aB0 + ro + ko);
            ldsm4(a1, aB1 + ro + ko);
            ldsm4(b01, bB01 + wo + ko);
            ldsm2(bb2, bB2 + wo + ko);
            mma_f16(acc[0][0], a0, b01[0], b01[1]);
            mma_f16(acc[0][1], a0, b01[2], b01[3]);
            mma_f16(acc[0][2], a0, bb2[0], bb2[1]);
            mma_f16(acc[1][0], a1, b01[0], b01[1]);
            mma_f16(acc[1][1], a1, b01[2], b01[3]);
            mma_f16(acc[1][2], a1, bb2[0], bb2[1]);
        }
    }

    {
        __half* dst = g_h2 + (size_t)(blockIdx.x * 4 + lp_w) * 1280;
        #pragma unroll
        for (int mt = 0; mt < 2; mt++) {
            const int row = hf * 32 + mt * 16 + g;
            #pragma unroll
            for (int nt = 0; nt < 3; nt++) {
                const int col = nt * 8 + tig * 2;
                if (col < 20) {
                    const float b0 = sB2[col], b1v = sB2[col + 1];
                    *(uint32_t*)&dst[row * 20 + col] =
                        pack_h2(fmaxf(acc[mt][nt][0] + b0, 0.f),
                                fmaxf(acc[mt][nt][1] + b1v, 0.f));
                    *(uint32_t*)&dst[(row + 8) * 20 + col] =
                        pack_h2(fmaxf(acc[mt][nt][2] + b0, 0.f),
                                fmaxf(acc[mt][nt][3] + b1v, 0.f));
                }
            }
        }
    }
}

// ===========================================================================
// Kernel 2: fused MLP, M=64/CTA, 256 threads, ~110KB smem -> 2 CTAs/SM
// 8 warps (2 wm x 4 wn), warp tile 32 x 64. cp.async 3-buf depth-2 pipeline.
// ===========================================================================
#define ML_ACT  0                       // 64 x 264 halves = 33792
#define ML_B    33792                   // 3 x (256 x 40 halves) = 3 x 20480
#define ML_A    (33792 + 61440)         // 3 x (64 x 40 halves)  = 3 x 5120
#define ML_SMEM (33792 + 61440 + 15360) // 110592

__global__ __launch_bounds__(256, 2) void mlp_mma_kernel(
    const float* __restrict__ fc1_b, const float* __restrict__ fc2_b,
    const float* __restrict__ fc3_b, const float* __restrict__ fcf_b,
    float* __restrict__ out)
{
    extern __shared__ __align__(16) char smc[];
    __half* sAct = (__half*)(smc + ML_ACT);

    const int tid  = threadIdx.x;
    const int l    = tid & 31;
    const int wid  = tid >> 5;
    const int wm   = wid >> 2;          // 0..1
    const int wn   = wid & 3;           // 0..3
    const int g    = l >> 2;
    const int tig  = l & 3;
    const int m0   = blockIdx.x * 64;

    const uint32_t sActu = s2u(smc + ML_ACT);
    const uint32_t sBu   = s2u(smc + ML_B);
    const uint32_t sAu   = s2u(smc + ML_A);

    const int l16 = l & 15, lg = l >> 4;
    const uint32_t relA0 = (uint32_t)((wm * 32 + l16) * 40 + lg * 8) * 2;
    const uint32_t relA1 = relA0 + 16 * 40 * 2;
    const uint32_t cA0 = sActu + (uint32_t)((wm * 32 + l16) * 264 + lg * 8) * 2;
    const uint32_t cA1 = cA0 + 16 * 264 * 2;
    const int bt = l >> 3;
    const int bnl = (bt >> 1) * 8 + (l & 7);
    const int bkl = (bt & 1) * 8;
    uint32_t relB[4];
    #pragma unroll
    for (int gn = 0; gn < 4; gn++)
        relB[gn] = (uint32_t)((wn * 64 + gn * 16 + bnl) * 40 + bkl) * 2;

    // staging: B rows 0..255 (1 row/thread, 4 quads); A rows 0..63 (4 thr/row)
    const int rA = tid >> 2, qA = tid & 3;

    float acc[2][8][4];

    // ================= fc1: K=1280, 40 chunks, A from g_h2 =================
    {
        #pragma unroll
        for (int mt = 0; mt < 2; mt++)
            #pragma unroll
            for (int nt = 0; nt < 8; nt++)
                #pragma unroll
                for (int q = 0; q < 4; q++) acc[mt][nt][q] = 0.f;

        auto issue1 = [&](int c) {
            const uint32_t bb = sBu + (uint32_t)(c % 3) * 20480;
            const uint32_t ab = sAu + (uint32_t)(c % 3) * 5120;
            const __half* bsrc = g_fc1h + (size_t)tid * 1280 + c * 32;
            #pragma unroll
            for (int q = 0; q < 4; q++)
                cp16(bb + (uint32_t)(tid * 40 + q * 8) * 2, bsrc + q * 8);
            cp16(ab + (uint32_t)(rA * 40 + qA * 8) * 2,
                 g_h2 + (size_t)(m0 + rA) * 1280 + c * 32 + qA * 8);
            CP_COMMIT();
        };
        issue1(0); issue1(1);

        for (int c = 0; c < 40; c++) {
            if (c + 2 < 40) { CP_WAIT1(); } else { CP_WAIT0(); }
            __syncthreads();
            if (c + 2 < 40) issue1(c + 2);
            const uint32_t bb = sBu + (uint32_t)(c % 3) * 20480;
            const uint32_t ab = sAu + (uint32_t)(c % 3) * 5120;
            #pragma unroll
            for (int kk = 0; kk < 32; kk += 16) {
                uint32_t a0[4], a1[4];
                ldsm4(a0, ab + relA0 + kk * 2);
                ldsm4(a1, ab + relA1 + kk * 2);
                #pragma unroll
                for (int gn = 0; gn < 4; gn++) {
                    uint32_t bbv[4];
                    ldsm4(bbv, bb + relB[gn] + kk * 2);
                    mma_f16(acc[0][2 * gn],     a0, bbv[0], bbv[1]);
                    mma_f16(acc[0][2 * gn + 1], a0, bbv[2], bbv[3]);
                    mma_f16(acc[1][2 * gn],     a1, bbv[0], bbv[1]);
                    mma_f16(acc[1][2 * gn + 1], a1, bbv[2], bbv[3]);
                }
            }
        }
        __syncthreads();
        #pragma unroll
        for (int mt = 0; mt < 2; mt++)
            #pragma unroll
            for (int nt = 0; nt < 8; nt++) {
                const int row = wm * 32 + mt * 16 + g;
                const int col = wn * 64 + nt * 8 + tig * 2;
                const float b0 = fc1_b[col], b1 = fc1_b[col + 1];
                *(uint32_t*)&sAct[row * 264 + col] =
                    pack_h2(fmaxf(acc[mt][nt][0] + b0, 0.f),
                            fmaxf(acc[mt][nt][1] + b1, 0.f));
                *(uint32_t*)&sAct[(row + 8) * 264 + col] =
                    pack_h2(fmaxf(acc[mt][nt][2] + b0, 0.f),
                            fmaxf(acc[mt][nt][3] + b1, 0.f));
            }
        __syncthreads();
    }

    // ================= fc2 & fc3: K=256, 8 chunks =================
    for (int layer = 0; layer < 2; layer++) {
        const __half* wg = layer ? g_fc3h : g_fc2h;
        const float*  bg = layer ? fc3_b : fc2_b;
        #pragma unroll
        for (int mt = 0; mt < 2; mt++)
            #pragma unroll
            for (int nt = 0; nt < 8; nt++)
                #pragma unroll
                for (int q = 0; q < 4; q++) acc[mt][nt][q] = 0.f;

        auto issue2 = [&](int c) {
            const uint32_t bb = sBu + (uint32_t)(c % 3) * 20480;
            const __half* bsrc = wg + (size_t)tid * 256 + c * 32;
            #pragma unroll
            for (int q = 0; q < 4; q++)
                cp16(bb + (uint32_t)(tid * 40 + q * 8) * 2, bsrc + q * 8);
            CP_COMMIT();
        };
        issue2(0); issue2(1);

        for (int c = 0; c < 8; c++) {
            if (c + 2 < 8) { CP_WAIT1(); } else { CP_WAIT0(); }
            __syncthreads();
            if (c + 2 < 8) issue2(c + 2);
            const uint32_t bb = sBu + (uint32_t)(c % 3) * 20480;
            #pragma unroll
            for (int kk = 0; kk < 32; kk += 16) {
                const int kg = c * 32 + kk;
                uint32_t a0[4], a1[4];
                ldsm4(a0, cA0 + kg * 2);
                ldsm4(a1, cA1 + kg * 2);
                #pragma unroll
                for (int gn = 0; gn < 4; gn++) {
                    uint32_t bbv[4];
                    ldsm4(bbv, bb + relB[gn] + kk * 2);
                    mma_f16(acc[0][2 * gn],     a0, bbv[0], bbv[1]);
                    mma_f16(acc[0][2 * gn + 1], a0, bbv[2], bbv[3]);
                    mma_f16(acc[1][2 * gn],     a1, bbv[0], bbv[1]);
                    mma_f16(acc[1][2 * gn + 1], a1, bbv[2], bbv[3]);
                }
            }
        }
        __syncthreads();
        #pragma unroll
        for (int mt = 0; mt < 2; mt++)
            #pragma unroll
            for (int nt = 0; nt < 8; nt++) {
                const int row = wm * 32 + mt * 16 + g;
                const int col = wn * 64 + nt * 8 + tig * 2;
                const float b0 = bg[col], b1 = bg[col + 1];
                *(uint32_t*)&sAct[row * 264 + col] =
                    pack_h2(fmaxf(acc[mt][nt][0] + b0, 0.f),
                            fmaxf(acc[mt][nt][1] + b1, 0.f));
                *(uint32_t*)&sAct[(row + 8) * 264 + col] =
                    pack_h2(fmaxf(acc[mt][nt][2] + b0, 0.f),
                            fmaxf(acc[mt][nt][3] + b1, 0.f));
            }
        __syncthreads();
    }

    // ================= fcf: K=256, N=27 (pad 32) =================
    {
        __half* sB0 = (__half*)(smc + ML_B);
        for (int i = tid; i < 1056; i += 256)
            ((uint4*)sB0)[i] = ((const uint4*)g_fcfh)[i];
        __syncthreads();

        const int l2b = l & 15;
        const uint32_t bF = sBu +
            (uint32_t)((wn * 8 + (l2b & 7)) * 264 + ((l2b >> 3) & 1) * 8) * 2;

        float fa[2][4];
        #pragma unroll
        for (int mt = 0; mt < 2; mt++)
            #pragma unroll
            for (int q = 0; q < 4; q++) fa[mt][q] = 0.f;

        #pragma unroll 4
        for (int s = 0; s < 16; s++) {
            const int kg = s * 16;
            uint32_t a0[4], a1[4], bb[2];
            ldsm4(a0, cA0 + kg * 2);
            ldsm4(a1, cA1 + kg * 2);
            ldsm2(bb, bF + kg * 2);
            mma_f16(fa[0], a0, bb[0], bb[1]);
            mma_f16(fa[1], a1, bb[0], bb[1]);
        }

        #pragma unroll
        for (int mt = 0; mt < 2; mt++) {
            const int row = m0 + wm * 32 + mt * 16 + g;
            const int col = wn * 8 + tig * 2;
            #pragma unroll
            for (int h = 0; h < 2; h++) {
                const int rr = row + h * 8;
                if (rr < NP) {
                    if (col < 27)
                        out[(size_t)rr * 27 + col]     = fa[mt][h * 2 + 0] + fcf_b[col];
                    if (col + 1 < 27)
                        out[(size_t)rr * 27 + col + 1] = fa[mt][h * 2 + 1] + fcf_b[col + 1];
                }
            }
        }
    }
}

// ---------------------------------------------------------------------------
extern "C" void kernel_launch(void* const* d_in, const int* in_sizes, int n_in,
                              void* d_out, int out_size)
{
    const float* images  = (const float*)d_in[0];
    const float* conv1_w = (const float*)d_in[1];
    const float* conv1_b = (const float*)d_in[2];
    const float* conv2_w = (const float*)d_in[3];
    const float* conv2_b = (const float*)d_in[4];
    const float* fc1_w   = (const float*)d_in[5];
    const float* fc1_b   = (const float*)d_in[6];
    const float* fc2_w   = (const float*)d_in[7];
    const float* fc2_b   = (const float*)d_in[8];
    const float* fc3_w   = (const float*)d_in[9];
    const float* fc3_b   = (const float*)d_in[10];
    const float* fcf_w   = (const float*)d_in[11];
    const float* fcf_b   = (const float*)d_in[12];
    float* out = (float*)d_out;

    convert_kernel<<<1280, 256>>>(fc1_w, fc2_w, fc3_w, fcf_w, conv2_w, conv1_w);

    cudaFuncSetAttribute(conv_mma_kernel,
                         cudaFuncAttributeMaxDynamicSharedMemorySize, CV_SMEM);
    conv_mma_kernel<<<NP / 4, 256, CV_SMEM>>>(images, conv1_b, conv2_b);

    cudaFuncSetAttribute(mlp_mma_kernel,
                         cudaFuncAttributeMaxDynamicSharedMemorySize, ML_SMEM);
    mlp_mma_kernel<<<MROWS_PAD / 64, 256, ML_SMEM>>>(
        fc1_b, fc2_b, fc3_b, fcf_b, out);
}

// round 16
// speedup vs baseline: 1.4905x; 1.4905x over previous
#include <cuda_runtime.h>
#include <cuda_fp16.h>
#include <cstdint>

#define NP 76832          // 32 * 49 * 49 patches
#define HN 49
#define SLEN 104
#define MROWS_PAD 76928   // 601 * 128

// conv output scratch, fp16, layout [patch][pix*20 + oc] (zero-init; pad rows zero)
__device__ __half g_h2[(size_t)MROWS_PAD * 1280];
// pre-converted fp16 weights
__device__ __align__(16) __half g_fc1h[256 * 1280];   // K permuted to pix*20+oc
__device__ __align__(16) __half g_fc2h[256 * 256];
__device__ __align__(16) __half g_fc3h[256 * 256];
__device__ __align__(16) __half g_fcfh[32 * 264];     // zero-padded
__device__ __align__(16) __half g_w2h[3 * 24 * 80];   // [dy][oc][dx*24+ic], zero-pad
__device__ __align__(16) __half g_w1h[3 * 24 * 32];   // [dy][oc][dx*8+ic], zero-pad

// ---------------------------------------------------------------------------
__device__ __forceinline__ uint32_t s2u(const void* p) {
    return (uint32_t)__cvta_generic_to_shared(p);
}
__device__ __forceinline__ void ldsm4(uint32_t* r, uint32_t addr) {
    asm volatile("ldmatrix.sync.aligned.m8n8.x4.shared.b16 {%0,%1,%2,%3}, [%4];"
        : "=r"(r[0]), "=r"(r[1]), "=r"(r[2]), "=r"(r[3]) : "r"(addr));
}
__device__ __forceinline__ void ldsm2(uint32_t* r, uint32_t addr) {
    asm volatile("ldmatrix.sync.aligned.m8n8.x2.shared.b16 {%0,%1}, [%2];"
        : "=r"(r[0]), "=r"(r[1]) : "r"(addr));
}
__device__ __forceinline__ void mma_f16(float* c, const uint32_t* a,
                                        uint32_t b0, uint32_t b1) {
    asm volatile(
        "mma.sync.aligned.m16n8k16.row.col.f32.f16.f16.f32 "
        "{%0,%1,%2,%3}, {%4,%5,%6,%7}, {%8,%9}, {%0,%1,%2,%3};"
        : "+f"(c[0]), "+f"(c[1]), "+f"(c[2]), "+f"(c[3])
        : "r"(a[0]), "r"(a[1]), "r"(a[2]), "r"(a[3]), "r"(b0), "r"(b1));
}
__device__ __forceinline__ uint32_t pack_h2(float a, float b) {
    __half2 h = __floats2half2_rn(a, b);
    return *(uint32_t*)&h;
}
__device__ __forceinline__ void cp16(uint32_t dst, const void* src) {
    asm volatile("cp.async.ca.shared.global [%0], [%1], 16;"
        :: "r"(dst), "l"(src));
}
#define CP_COMMIT() asm volatile("cp.async.commit_group;" ::: "memory")
#define CP_WAIT0()  asm volatile("cp.async.wait_group 0;" ::: "memory")
#define CP_WAIT1()  asm volatile("cp.async.wait_group 1;" ::: "memory")

// ===========================================================================
// Kernel 0: one-shot fp16 weight conversion / re-layout
// ===========================================================================
__global__ __launch_bounds__(256) void convert_kernel(
    const float* __restrict__ fc1_w, const float* __restrict__ fc2_w,
    const float* __restrict__ fc3_w, const float* __restrict__ fcf_w,
    const float* __restrict__ w2, const float* __restrict__ w1)
{
    const int i = blockIdx.x * 256 + threadIdx.x;
    if (i < 256 * 1280) {
        int n = i / 1280, k = i % 1280;
        int oc = k / 64, pix = k % 64;
        g_fc1h[(size_t)n * 1280 + pix * 20 + oc] = __float2half(fc1_w[i]);
    }
    if (i < 256 * 256) {
        g_fc2h[i] = __float2half(fc2_w[i]);
        g_fc3h[i] = __float2half(fc3_w[i]);
    }
    if (i < 32 * 264) {
        int r = i / 264, k = i % 264;
        g_fcfh[i] = (r < 27 && k < 256) ? __float2half(fcf_w[r * 256 + k])
                                        : __half(0.f);
    }
    if (i < 3 * 24 * 80) {
        int dy = i / 1920, r = i % 1920, oc = r / 80, k = r % 80;
        int dx = k / 24, ic = k % 24;
        g_w2h[i] = (oc < 20 && k < 72 && ic < 20)
                 ? __float2half(w2[oc * 180 + ic * 9 + dy * 3 + dx]) : __half(0.f);
    }
    if (i < 3 * 24 * 32) {
        int dy = i / 768, r = i % 768, oc = r / 32, k = r % 32;
        int dx = k / 8, ic = k % 8;
        g_w1h[i] = (oc < 20 && dx < 3 && ic < 2)
                 ? __float2half(w1[oc * 18 + ic * 9 + dy * 3 + dx]) : __half(0.f);
    }
}

// ===========================================================================
// Kernel 1: persistent conv — each CTA handles 8 groups of 4 patches.
// Weights copied + pads zeroed ONCE, then loop. 256 threads = 8 warps.
// ===========================================================================
#define NITER   8
#define CV_H1   0
#define CV_W2   19232
#define CV_INH  30752
#define CV_W1H  37152
#define CV_B1   41760
#define CV_B2   41856
#define CV_SMEM 41952

__global__ __launch_bounds__(256) void conv_mma_kernel(
    const float* __restrict__ images,
    const float* __restrict__ b1, const float* __restrict__ b2)
{
    extern __shared__ __align__(16) char smc[];
    __half* sH1  = (__half*)(smc + CV_H1);
    __half* sW2  = (__half*)(smc + CV_W2);
    __half* sInH = (__half*)(smc + CV_INH);
    __half* sW1h = (__half*)(smc + CV_W1H);
    float*  sB1  = (float*)(smc + CV_B1);
    float*  sB2  = (float*)(smc + CV_B2);

    const int tid = threadIdx.x;

    // one-time setup: zero pads, copy weights
    {
        uint32_t* z = (uint32_t*)smc;
        for (int i = tid; i < 19232 / 4; i += 256) z[i] = 0u;
        uint32_t* z2 = (uint32_t*)(smc + CV_INH);
        for (int i = tid; i < 6400 / 4; i += 256) z2[i] = 0u;
    }
    for (int i = tid; i < 720; i += 256)
        ((uint4*)sW2)[i] = ((const uint4*)g_w2h)[i];
    for (int i = tid; i < 288; i += 256)
        ((uint4*)sW1h)[i] = ((const uint4*)g_w1h)[i];
    if (tid < 24) {
        sB1[tid] = (tid < 20) ? b1[tid] : 0.f;
        sB2[tid] = (tid < 20) ? b2[tid] : 0.f;
    }

    // per-thread geometry (loop-invariant)
    const int lp  = tid >> 6;          // 0..3 (input-loader patch)
    const int pix = tid & 63;
    const int y = pix >> 3, x = pix & 7;
    const int inoff = lp * 800 + ((y + 1) * 10 + (x + 1)) * 8;

    const int l    = tid & 31;
    const int wid  = tid >> 5;
    const int lp_w = wid >> 1;
    const int hf   = wid & 1;
    const int g    = l >> 2;
    const int tig  = l & 3;
    const int l16  = l & 15, lg = l >> 4;

    const int pA0 = hf * 32 + l16;
    const int pA1 = pA0 + 16;
    const int rT0 = (pA0 >> 3) * 10 + (pA0 & 7);
    const int rT1 = (pA1 >> 3) * 10 + (pA1 & 7);

    const int bt   = l >> 3;
    const int bn01 = (bt >> 1) * 8 + (l & 7);
    const int bk01 = (bt & 1) * 8;
    const int l2   = l & 15;
    const int bn2  = 16 + (l2 & 7);
    const int bk2  = ((l2 >> 3) & 1) * 8;

    const uint32_t sInU = s2u(sInH + lp_w * 800);
    const uint32_t sW1u = s2u(sW1h);
    const uint32_t aI0 = sInU + (uint32_t)(rT0 * 8 + lg * 8) * 2;
    const uint32_t aI1 = sInU + (uint32_t)(rT1 * 8 + lg * 8) * 2;
    const uint32_t bW10 = sW1u + (uint32_t)(bn01 * 32 + bk01) * 2;
    const uint32_t bW12 = sW1u + (uint32_t)(bn2 * 32 + bk2) * 2;

    const uint32_t sH1u = s2u(sH1 + lp_w * 2400);
    const uint32_t sW2u = s2u(sW2);
    const uint32_t aB0 = sH1u + (uint32_t)(rT0 * 24 + lg * 8) * 2;
    const uint32_t aB1 = sH1u + (uint32_t)(rT1 * 24 + lg * 8) * 2;
    const uint32_t bB01 = sW2u + (uint32_t)(bn01 * 80 + bk01) * 2;
    const uint32_t bB2  = sW2u + (uint32_t)(bn2 * 80 + bk2) * 2;

    // prefetch input for iter 0
    const int base_patch = blockIdx.x * (4 * NITER);
    float c0, c1;
    {
        const int patch = base_patch + lp;
        const int b  = patch / (HN * HN);
        const int t2 = patch % (HN * HN);
        const int i0 = (t2 / HN) * 2, j0 = (t2 % HN) * 2;
        c0 = images[((size_t)(b * 2 + 0) * SLEN + (i0 + y)) * SLEN + (j0 + x)];
        c1 = images[((size_t)(b * 2 + 1) * SLEN + (i0 + y)) * SLEN + (j0 + x)];
    }

    for (int iter = 0; iter < NITER; iter++) {
        __syncthreads();   // prev conv1 reads of sInH done (and setup on iter 0)
        *(uint32_t*)&sInH[inoff] = pack_h2(c0, c1);
        if (iter + 1 < NITER) {
            const int patch = base_patch + (iter + 1) * 4 + lp;
            const int b  = patch / (HN * HN);
            const int t2 = patch % (HN * HN);
            const int i0 = (t2 / HN) * 2, j0 = (t2 % HN) * 2;
            c0 = images[((size_t)(b * 2 + 0) * SLEN + (i0 + y)) * SLEN + (j0 + x)];
            c1 = images[((size_t)(b * 2 + 1) * SLEN + (i0 + y)) * SLEN + (j0 + x)];
        }
        __syncthreads();

        // ---- conv1 ----
        {
            float acc1[2][3][4];
            #pragma unroll
            for (int mt = 0; mt < 2; mt++)
                #pragma unroll
                for (int nt = 0; nt < 3; nt++)
                    #pragma unroll
                    for (int q = 0; q < 4; q++) acc1[mt][nt][q] = 0.f;

            #pragma unroll
            for (int dy = 0; dy < 3; dy++) {
                const uint32_t ro = (uint32_t)dy * 160;
                const uint32_t wo = (uint32_t)dy * 1536;
                #pragma unroll
                for (int c = 0; c < 2; c++) {
                    const uint32_t ko = (uint32_t)c * 32;
                    uint32_t a0[4], a1[4], b01[4], bb2[2];
                    ldsm4(a0, aI0 + ro + ko);
                    ldsm4(a1, aI1 + ro + ko);
                    ldsm4(b01, bW10 + wo + ko);
                    ldsm2(bb2, bW12 + wo + ko);
                    mma_f16(acc1[0][0], a0, b01[0], b01[1]);
                    mma_f16(acc1[0][1], a0, b01[2], b01[3]);
                    mma_f16(acc1[0][2], a0, bb2[0], bb2[1]);
                    mma_f16(acc1[1][0], a1, b01[0], b01[1]);
                    mma_f16(acc1[1][1], a1, b01[2], b01[3]);
                    mma_f16(acc1[1][2], a1, bb2[0], bb2[1]);
                }
            }

            __half* h1w = sH1 + lp_w * 2400;
            #pragma unroll
            for (int mt = 0; mt < 2; mt++) {
                const int row = hf * 32 + mt * 16 + g;
                const int rc0 = ((row >> 3) + 1) * 10 + (row & 7) + 1;
                const int rc1 = (((row + 8) >> 3) + 1) * 10 + (row & 7) + 1;
                #pragma unroll
                for (int nt = 0; nt < 3; nt++) {
                    const int col = nt * 8 + tig * 2;
                    if (col < 20) {
                        const float v0 = sB1[col], v1 = sB1[col + 1];
                        *(uint32_t*)&h1w[rc0 * 24 + col] =
                            pack_h2(fmaxf(acc1[mt][nt][0] + v0, 0.f),
                                    fmaxf(acc1[mt][nt][1] + v1, 0.f));
                        *(uint32_t*)&h1w[rc1 * 24 + col] =
                            pack_h2(fmaxf(acc1[mt][nt][2] + v0, 0.f),
                                    fmaxf(acc1[mt][nt][3] + v1, 0.f));
                    }
                }
            }
        }
        __syncthreads();

        // ---- conv2 ----
        {
            float acc[2][3][4];
            #pragma unroll
            for (int mt = 0; mt < 2; mt++)
                #pragma unroll
                for (int nt = 0; nt < 3; nt++)
                    #pragma unroll
                    for (int q = 0; q < 4; q++) acc[mt][nt][q] = 0.f;

            #pragma unroll
            for (int dy = 0; dy < 3; dy++) {
                const uint32_t ro = (uint32_t)dy * 480;
                const uint32_t wo = (uint32_t)dy * 3840;
                #pragma unroll
                for (int c = 0; c < 5; c++) {
                    const uint32_t ko = (uint32_t)c * 32;
                    uint32_t a0[4], a1[4], b01[4], bb2[2];
                    ldsm4(a0, aB0 + ro + ko);
                    ldsm4(a1, aB1 + ro + ko);
                    ldsm4(b01, bB01 + wo + ko);
                    ldsm2(bb2, bB2 + wo + ko);
                    mma_f16(acc[0][0], a0, b01[0], b01[1]);
                    mma_f16(acc[0][1], a0, b01[2], b01[3]);
                    mma_f16(acc[0][2], a0, bb2[0], bb2[1]);
                    mma_f16(acc[1][0], a1, b01[0], b01[1]);
                    mma_f16(acc[1][1], a1, b01[2], b01[3]);
                    mma_f16(acc[1][2], a1, bb2[0], bb2[1]);
                }
            }

            __half* dst = g_h2 + (size_t)(base_patch + iter * 4 + lp_w) * 1280;
            #pragma unroll
            for (int mt = 0; mt < 2; mt++) {
                const int row = hf * 32 + mt * 16 + g;
                #pragma unroll
                for (int nt = 0; nt < 3; nt++) {
                    const int col = nt * 8 + tig * 2;
                    if (col < 20) {
                        const float b0 = sB2[col], b1v = sB2[col + 1];
                        *(uint32_t*)&dst[row * 20 + col] =
                            pack_h2(fmaxf(acc[mt][nt][0] + b0, 0.f),
                                    fmaxf(acc[mt][nt][1] + b1v, 0.f));
                        *(uint32_t*)&dst[(row + 8) * 20 + col] =
                            pack_h2(fmaxf(acc[mt][nt][2] + b0, 0.f),
                                    fmaxf(acc[mt][nt][3] + b1v, 0.f));
                    }
                }
            }
        }
    }
}

// ===========================================================================
// Kernel 2: fused MLP (exact R11 config: M=128, 512 thr, 3-buf cp.async)
// ===========================================================================
#define ML_ACT  0                       // 128 x 264 halves = 67584
#define ML_B    67584                   // 3 x (256 x 40 halves) = 3 x 20480
#define ML_A    (67584 + 61440)         // 3 x (128 x 40 halves) = 3 x 10240
#define ML_SMEM (67584 + 61440 + 30720) // 159744

__global__ __launch_bounds__(512, 1) void mlp_mma_kernel(
    const float* __restrict__ fc1_b, const float* __restrict__ fc2_b,
    const float* __restrict__ fc3_b, const float* __restrict__ fcf_b,
    float* __restrict__ out)
{
    extern __shared__ __align__(16) char smc[];
    __half* sAct = (__half*)(smc + ML_ACT);

    const int tid  = threadIdx.x;
    const int l    = tid & 31;
    const int wid  = tid >> 5;
    const int wm   = wid >> 2;
    const int wn   = wid & 3;
    const int g    = l >> 2;
    const int tig  = l & 3;
    const int m0   = blockIdx.x * 128;

    const uint32_t sActu = s2u(smc + ML_ACT);
    const uint32_t sBu   = s2u(smc + ML_B);
    const uint32_t sAu   = s2u(smc + ML_A);

    const int l16 = l & 15, lg = l >> 4;
    const uint32_t relA0 = (uint32_t)((wm * 32 + l16) * 40 + lg * 8) * 2;
    const uint32_t relA1 = relA0 + 16 * 40 * 2;
    const uint32_t cA0 = sActu + (uint32_t)((wm * 32 + l16) * 264 + lg * 8) * 2;
    const uint32_t cA1 = cA0 + 16 * 264 * 2;
    const int bt = l >> 3;
    const int bnl = (bt >> 1) * 8 + (l & 7);
    const int bkl = (bt & 1) * 8;
    uint32_t relB[4];
    #pragma unroll
    for (int gn = 0; gn < 4; gn++)
        relB[gn] = (uint32_t)((wn * 64 + gn * 16 + bnl) * 40 + bkl) * 2;

    const int rB = tid >> 1, ofB = (tid & 1) * 16;
    const int rA = tid >> 2, qA = tid & 3;

    float acc[2][8][4];

    // ================= fc1: K=1280, 40 chunks, A from g_h2 =================
    {
        #pragma unroll
        for (int mt = 0; mt < 2; mt++)
            #pragma unroll
            for (int nt = 0; nt < 8; nt++)
                #pragma unroll
                for (int q = 0; q < 4; q++) acc[mt][nt][q] = 0.f;

        auto issue1 = [&](int c) {
            const uint32_t bb = sBu + (uint32_t)(c % 3) * 20480;
            const uint32_t ab = sAu + (uint32_t)(c % 3) * 10240;
            const __half* bsrc = g_fc1h + (size_t)rB * 1280 + c * 32 + ofB;
            cp16(bb + (uint32_t)(rB * 40 + ofB) * 2, bsrc);
            cp16(bb + (uint32_t)(rB * 40 + ofB + 8) * 2, bsrc + 8);
            cp16(ab + (uint32_t)(rA * 40 + qA * 8) * 2,
                 g_h2 + (size_t)(m0 + rA) * 1280 + c * 32 + qA * 8);
            CP_COMMIT();
        };
        issue1(0); issue1(1);

        for (int c = 0; c < 40; c++) {
            if (c + 2 < 40) { CP_WAIT1(); } else { CP_WAIT0(); }
            __syncthreads();
            if (c + 2 < 40) issue1(c + 2);
            const uint32_t bb = sBu + (uint32_t)(c % 3) * 20480;
            const uint32_t ab = sAu + (uint32_t)(c % 3) * 10240;
            #pragma unroll
            for (int kk = 0; kk < 32; kk += 16) {
                uint32_t a0[4], a1[4];
                ldsm4(a0, ab + relA0 + kk * 2);
                ldsm4(a1, ab + relA1 + kk * 2);
                #pragma unroll
                for (int gn = 0; gn < 4; gn++) {
                    uint32_t bbv[4];
                    ldsm4(bbv, bb + relB[gn] + kk * 2);
                    mma_f16(acc[0][2 * gn],     a0, bbv[0], bbv[1]);
                    mma_f16(acc[0][2 * gn + 1], a0, bbv[2], bbv[3]);
                    mma_f16(acc[1][2 * gn],     a1, bbv[0], bbv[1]);
                    mma_f16(acc[1][2 * gn + 1], a1, bbv[2], bbv[3]);
                }
            }
        }
        __syncthreads();
        #pragma unroll
        for (int mt = 0; mt < 2; mt++)
            #pragma unroll
            for (int nt = 0; nt < 8; nt++) {
                const int row = wm * 32 + mt * 16 + g;
                const int col = wn * 64 + nt * 8 + tig * 2;
                const float b0 = fc1_b[col], b1 = fc1_b[col + 1];
                *(uint32_t*)&sAct[row * 264 + col] =
                    pack_h2(fmaxf(acc[mt][nt][0] + b0, 0.f),
                            fmaxf(acc[mt][nt][1] + b1, 0.f));
                *(uint32_t*)&sAct[(row + 8) * 264 + col] =
                    pack_h2(fmaxf(acc[mt][nt][2] + b0, 0.f),
                            fmaxf(acc[mt][nt][3] + b1, 0.f));
            }
        __syncthreads();
    }

    // ================= fc2 & fc3: K=256, 8 chunks =================
    for (int layer = 0; layer < 2; layer++) {
        const __half* wg = layer ? g_fc3h : g_fc2h;
        const float*  bg = layer ? fc3_b : fc2_b;
        #pragma unroll
        for (int mt = 0; mt < 2; mt++)
            #pragma unroll
            for (int nt = 0; nt < 8; nt++)
                #pragma unroll
                for (int q = 0; q < 4; q++) acc[mt][nt][q] = 0.f;

        auto issue2 = [&](int c) {
            const uint32_t bb = sBu + (uint32_t)(c % 3) * 20480;
            const __half* bsrc = wg + (size_t)rB * 256 + c * 32 + ofB;
            cp16(bb + (uint32_t)(rB * 40 + ofB) * 2, bsrc);
            cp16(bb + (uint32_t)(rB * 40 + ofB + 8) * 2, bsrc + 8);
            CP_COMMIT();
        };
        issue2(0); issue2(1);

        for (int c = 0; c < 8; c++) {
            if (c + 2 < 8) { CP_WAIT1(); } else { CP_WAIT0(); }
            __syncthreads();
            if (c + 2 < 8) issue2(c + 2);
            const uint32_t bb = sBu + (uint32_t)(c % 3) * 20480;
            #pragma unroll
            for (int kk = 0; kk < 32; kk += 16) {
                const int kg = c * 32 + kk;
                uint32_t a0[4], a1[4];
                ldsm4(a0, cA0 + kg * 2);
                ldsm4(a1, cA1 + kg * 2);
                #pragma unroll
                for (int gn = 0; gn < 4; gn++) {
                    uint32_t bbv[4];
                    ldsm4(bbv, bb + relB[gn] + kk * 2);
                    mma_f16(acc[0][2 * gn],     a0, bbv[0], bbv[1]);
                    mma_f16(acc[0][2 * gn + 1], a0, bbv[2], bbv[3]);
                    mma_f16(acc[1][2 * gn],     a1, bbv[0], bbv[1]);
                    mma_f16(acc[1][2 * gn + 1], a1, bbv[2], bbv[3]);
                }
            }
        }
        __syncthreads();
        #pragma unroll
        for (int mt = 0; mt < 2; mt++)
            #pragma unroll
            for (int nt = 0; nt < 8; nt++) {
                const int row = wm * 32 + mt * 16 + g;
                const int col = wn * 64 + nt * 8 + tig * 2;
                const float b0 = bg[col], b1 = bg[col + 1];
                *(uint32_t*)&sAct[row * 264 + col] =
                    pack_h2(fmaxf(acc[mt][nt][0] + b0, 0.f),
                            fmaxf(acc[mt][nt][1] + b1, 0.f));
                *(uint32_t*)&sAct[(row + 8) * 264 + col] =
                    pack_h2(fmaxf(acc[mt][nt][2] + b0, 0.f),
                            fmaxf(acc[mt][nt][3] + b1, 0.f));
            }
        __syncthreads();
    }

    // ================= fcf: K=256, N=27 (pad 32) =================
    {
        __half* sB0 = (__half*)(smc + ML_B);
        for (int i = tid; i < 1056; i += 512)
            ((uint4*)sB0)[i] = ((const uint4*)g_fcfh)[i];
        __syncthreads();

        const int l2b = l & 15;
        const uint32_t bF = sBu +
            (uint32_t)((wn * 8 + (l2b & 7)) * 264 + ((l2b >> 3) & 1) * 8) * 2;

        float fa[2][4];
        #pragma unroll
        for (int mt = 0; mt < 2; mt++)
            #pragma unroll
            for (int q = 0; q < 4; q++) fa[mt][q] = 0.f;

        #pragma unroll 4
        for (int s = 0; s < 16; s++) {
            const int kg = s * 16;
            uint32_t a0[4], a1[4], bb[2];
            ldsm4(a0, cA0 + kg * 2);
            ldsm4(a1, cA1 + kg * 2);
            ldsm2(bb, bF + kg * 2);
            mma_f16(fa[0], a0, bb[0], bb[1]);
            mma_f16(fa[1], a1, bb[0], bb[1]);
        }

        #pragma unroll
        for (int mt = 0; mt < 2; mt++) {
            const int row = m0 + wm * 32 + mt * 16 + g;
            const int col = wn * 8 + tig * 2;
            #pragma unroll
            for (int h = 0; h < 2; h++) {
                const int rr = row + h * 8;
                if (rr < NP) {
                    if (col < 27)
                        out[(size_t)rr * 27 + col]     = fa[mt][h * 2 + 0] + fcf_b[col];
                    if (col + 1 < 27)
                        out[(size_t)rr * 27 + col + 1] = fa[mt][h * 2 + 1] + fcf_b[col + 1];
                }
            }
        }
    }
}

// ---------------------------------------------------------------------------
extern "C" void kernel_launch(void* const* d_in, const int* in_sizes, int n_in,
                              void* d_out, int out_size)
{
    const float* images  = (const float*)d_in[0];
    const float* conv1_w = (const float*)d_in[1];
    const float* conv1_b = (const float*)d_in[2];
    const float* conv2_w = (const float*)d_in[3];
    const float* conv2_b = (const float*)d_in[4];
    const float* fc1_w   = (const float*)d_in[5];
    const float* fc1_b   = (const float*)d_in[6];
    const float* fc2_w   = (const float*)d_in[7];
    const float* fc2_b   = (const float*)d_in[8];
    const float* fc3_w   = (const float*)d_in[9];
    const float* fc3_b   = (const float*)d_in[10];
    const float* fcf_w   = (const float*)d_in[11];
    const float* fcf_b   = (const float*)d_in[12];
    float* out = (float*)d_out;

    convert_kernel<<<1280, 256>>>(fc1_w, fc2_w, fc3_w, fcf_w, conv2_w, conv1_w);

    cudaFuncSetAttribute(conv_mma_kernel,
                         cudaFuncAttributeMaxDynamicSharedMemorySize, CV_SMEM);
    conv_mma_kernel<<<NP / (4 * NITER), 256, CV_SMEM>>>(images, conv1_b, conv2_b);

    cudaFuncSetAttribute(mlp_mma_kernel,
                         cudaFuncAttributeMaxDynamicSharedMemorySize, ML_SMEM);
    mlp_mma_kernel<<<MROWS_PAD / 128, 512, ML_SMEM>>>(
        fc1_b, fc2_b, fc3_b, fcf_b, out);
}

// round 17
// speedup vs baseline: 1.5118x; 1.0143x over previous
#include <cuda_runtime.h>
#include <cuda_fp16.h>
#include <cstdint>

#define NP 76832          // 32 * 49 * 49 patches
#define HN 49
#define SLEN 104
#define MROWS_PAD 76928   // 601 * 128

// conv output scratch, fp16, layout [patch][pix*20 + oc] (zero-init; pad rows zero)
__device__ __half g_h2[(size_t)MROWS_PAD * 1280];
// pre-converted fp16 weights
__device__ __align__(16) __half g_fc1h[256 * 1280];   // K permuted to pix*20+oc
__device__ __align__(16) __half g_fc2h[256 * 256];
__device__ __align__(16) __half g_fc3h[256 * 256];
__device__ __align__(16) __half g_fcfh[32 * 264];     // zero-padded
__device__ __align__(16) __half g_w2h[3 * 24 * 80];   // [dy][oc][dx*24+ic], zero-pad
__device__ __align__(16) __half g_w1h[3 * 24 * 32];   // [dy][oc][dx*8+ic], zero-pad

// ---------------------------------------------------------------------------
__device__ __forceinline__ uint32_t s2u(const void* p) {
    return (uint32_t)__cvta_generic_to_shared(p);
}
__device__ __forceinline__ void ldsm4(uint32_t* r, uint32_t addr) {
    asm volatile("ldmatrix.sync.aligned.m8n8.x4.shared.b16 {%0,%1,%2,%3}, [%4];"
        : "=r"(r[0]), "=r"(r[1]), "=r"(r[2]), "=r"(r[3]) : "r"(addr));
}
__device__ __forceinline__ void ldsm2(uint32_t* r, uint32_t addr) {
    asm volatile("ldmatrix.sync.aligned.m8n8.x2.shared.b16 {%0,%1}, [%2];"
        : "=r"(r[0]), "=r"(r[1]) : "r"(addr));
}
__device__ __forceinline__ void mma_f16(float* c, const uint32_t* a,
                                        uint32_t b0, uint32_t b1) {
    asm volatile(
        "mma.sync.aligned.m16n8k16.row.col.f32.f16.f16.f32 "
        "{%0,%1,%2,%3}, {%4,%5,%6,%7}, {%8,%9}, {%0,%1,%2,%3};"
        : "+f"(c[0]), "+f"(c[1]), "+f"(c[2]), "+f"(c[3])
        : "r"(a[0]), "r"(a[1]), "r"(a[2]), "r"(a[3]), "r"(b0), "r"(b1));
}
__device__ __forceinline__ uint32_t pack_h2(float a, float b) {
    __half2 h = __floats2half2_rn(a, b);
    return *(uint32_t*)&h;
}
__device__ __forceinline__ void cp16(uint32_t dst, const void* src) {
    asm volatile("cp.async.ca.shared.global [%0], [%1], 16;"
        :: "r"(dst), "l"(src));
}
#define CP_COMMIT() asm volatile("cp.async.commit_group;" ::: "memory")
#define CP_WAIT0()  asm volatile("cp.async.wait_group 0;" ::: "memory")

// ===========================================================================
// Kernel 0: one-shot fp16 weight conversion / re-layout
// ===========================================================================
__global__ __launch_bounds__(256) void convert_kernel(
    const float* __restrict__ fc1_w, const float* __restrict__ fc2_w,
    const float* __restrict__ fc3_w, const float* __restrict__ fcf_w,
    const float* __restrict__ w2, const float* __restrict__ w1)
{
    const int i = blockIdx.x * 256 + threadIdx.x;
    if (i < 256 * 1280) {
        int n = i / 1280, k = i % 1280;
        int oc = k / 64, pix = k % 64;
        g_fc1h[(size_t)n * 1280 + pix * 20 + oc] = __float2half(fc1_w[i]);
    }
    if (i < 256 * 256) {
        g_fc2h[i] = __float2half(fc2_w[i]);
        g_fc3h[i] = __float2half(fc3_w[i]);
    }
    if (i < 32 * 264) {
        int r = i / 264, k = i % 264;
        g_fcfh[i] = (r < 27 && k < 256) ? __float2half(fcf_w[r * 256 + k])
                                        : __half(0.f);
    }
    if (i < 3 * 24 * 80) {
        int dy = i / 1920, r = i % 1920, oc = r / 80, k = r % 80;
        int dx = k / 24, ic = k % 24;
        g_w2h[i] = (oc < 20 && k < 72 && ic < 20)
                 ? __float2half(w2[oc * 180 + ic * 9 + dy * 3 + dx]) : __half(0.f);
    }
    if (i < 3 * 24 * 32) {
        int dy = i / 768, r = i % 768, oc = r / 32, k = r % 32;
        int dx = k / 8, ic = k % 8;
        g_w1h[i] = (oc < 20 && dx < 3 && ic < 2)
                 ? __float2half(w1[oc * 18 + ic * 9 + dy * 3 + dx]) : __half(0.f);
    }
}

// ===========================================================================
// Kernel 1: persistent conv (unchanged R16 winner)
// ===========================================================================
#define NITER   8
#define CV_H1   0
#define CV_W2   19232
#define CV_INH  30752
#define CV_W1H  37152
#define CV_B1   41760
#define CV_B2   41856
#define CV_SMEM 41952

__global__ __launch_bounds__(256) void conv_mma_kernel(
    const float* __restrict__ images,
    const float* __restrict__ b1, const float* __restrict__ b2)
{
    extern __shared__ __align__(16) char smc[];
    __half* sH1  = (__half*)(smc + CV_H1);
    __half* sW2  = (__half*)(smc + CV_W2);
    __half* sInH = (__half*)(smc + CV_INH);
    __half* sW1h = (__half*)(smc + CV_W1H);
    float*  sB1  = (float*)(smc + CV_B1);
    float*  sB2  = (float*)(smc + CV_B2);

    const int tid = threadIdx.x;

    {
        uint32_t* z = (uint32_t*)smc;
        for (int i = tid; i < 19232 / 4; i += 256) z[i] = 0u;
        uint32_t* z2 = (uint32_t*)(smc + CV_INH);
        for (int i = tid; i < 6400 / 4; i += 256) z2[i] = 0u;
    }
    for (int i = tid; i < 720; i += 256)
        ((uint4*)sW2)[i] = ((const uint4*)g_w2h)[i];
    for (int i = tid; i < 288; i += 256)
        ((uint4*)sW1h)[i] = ((const uint4*)g_w1h)[i];
    if (tid < 24) {
        sB1[tid] = (tid < 20) ? b1[tid] : 0.f;
        sB2[tid] = (tid < 20) ? b2[tid] : 0.f;
    }

    const int lp  = tid >> 6;
    const int pix = tid & 63;
    const int y = pix >> 3, x = pix & 7;
    const int inoff = lp * 800 + ((y + 1) * 10 + (x + 1)) * 8;

    const int l    = tid & 31;
    const int wid  = tid >> 5;
    const int lp_w = wid >> 1;
    const int hf   = wid & 1;
    const int g    = l >> 2;
    const int tig  = l & 3;
    const int l16  = l & 15, lg = l >> 4;

    const int pA0 = hf * 32 + l16;
    const int pA1 = pA0 + 16;
    const int rT0 = (pA0 >> 3) * 10 + (pA0 & 7);
    const int rT1 = (pA1 >> 3) * 10 + (pA1 & 7);

    const int bt   = l >> 3;
    const int bn01 = (bt >> 1) * 8 + (l & 7);
    const int bk01 = (bt & 1) * 8;
    const int l2   = l & 15;
    const int bn2  = 16 + (l2 & 7);
    const int bk2  = ((l2 >> 3) & 1) * 8;

    const uint32_t sInU = s2u(sInH + lp_w * 800);
    const uint32_t sW1u = s2u(sW1h);
    const uint32_t aI0 = sInU + (uint32_t)(rT0 * 8 + lg * 8) * 2;
    const uint32_t aI1 = sInU + (uint32_t)(rT1 * 8 + lg * 8) * 2;
    const uint32_t bW10 = sW1u + (uint32_t)(bn01 * 32 + bk01) * 2;
    const uint32_t bW12 = sW1u + (uint32_t)(bn2 * 32 + bk2) * 2;

    const uint32_t sH1u = s2u(sH1 + lp_w * 2400);
    const uint32_t sW2u = s2u(sW2);
    const uint32_t aB0 = sH1u + (uint32_t)(rT0 * 24 + lg * 8) * 2;
    const uint32_t aB1 = sH1u + (uint32_t)(rT1 * 24 + lg * 8) * 2;
    const uint32_t bB01 = sW2u + (uint32_t)(bn01 * 80 + bk01) * 2;
    const uint32_t bB2  = sW2u + (uint32_t)(bn2 * 80 + bk2) * 2;

    const int base_patch = blockIdx.x * (4 * NITER);
    float c0, c1;
    {
        const int patch = base_patch + lp;
        const int b  = patch / (HN * HN);
        const int t2 = patch % (HN * HN);
        const int i0 = (t2 / HN) * 2, j0 = (t2 % HN) * 2;
        c0 = images[((size_t)(b * 2 + 0) * SLEN + (i0 + y)) * SLEN + (j0 + x)];
        c1 = images[((size_t)(b * 2 + 1) * SLEN + (i0 + y)) * SLEN + (j0 + x)];
    }

    for (int iter = 0; iter < NITER; iter++) {
        __syncthreads();
        *(uint32_t*)&sInH[inoff] = pack_h2(c0, c1);
        if (iter + 1 < NITER) {
            const int patch = base_patch + (iter + 1) * 4 + lp;
            const int b  = patch / (HN * HN);
            const int t2 = patch % (HN * HN);
            const int i0 = (t2 / HN) * 2, j0 = (t2 % HN) * 2;
            c0 = images[((size_t)(b * 2 + 0) * SLEN + (i0 + y)) * SLEN + (j0 + x)];
            c1 = images[((size_t)(b * 2 + 1) * SLEN + (i0 + y)) * SLEN + (j0 + x)];
        }
        __syncthreads();

        // ---- conv1 ----
        {
            float acc1[2][3][4];
            #pragma unroll
            for (int mt = 0; mt < 2; mt++)
                #pragma unroll
                for (int nt = 0; nt < 3; nt++)
                    #pragma unroll
                    for (int q = 0; q < 4; q++) acc1[mt][nt][q] = 0.f;

            #pragma unroll
            for (int dy = 0; dy < 3; dy++) {
                const uint32_t ro = (uint32_t)dy * 160;
                const uint32_t wo = (uint32_t)dy * 1536;
                #pragma unroll
                for (int c = 0; c < 2; c++) {
                    const uint32_t ko = (uint32_t)c * 32;
                    uint32_t a0[4], a1[4], b01[4], bb2[2];
                    ldsm4(a0, aI0 + ro + ko);
                    ldsm4(a1, aI1 + ro + ko);
                    ldsm4(b01, bW10 + wo + ko);
                    ldsm2(bb2, bW12 + wo + ko);
                    mma_f16(acc1[0][0], a0, b01[0], b01[1]);
                    mma_f16(acc1[0][1], a0, b01[2], b01[3]);
                    mma_f16(acc1[0][2], a0, bb2[0], bb2[1]);
                    mma_f16(acc1[1][0], a1, b01[0], b01[1]);
                    mma_f16(acc1[1][1], a1, b01[2], b01[3]);
                    mma_f16(acc1[1][2], a1, bb2[0], bb2[1]);
                }
            }

            __half* h1w = sH1 + lp_w * 2400;
            #pragma unroll
            for (int mt = 0; mt < 2; mt++) {
                const int row = hf * 32 + mt * 16 + g;
                const int rc0 = ((row >> 3) + 1) * 10 + (row & 7) + 1;
                const int rc1 = (((row + 8) >> 3) + 1) * 10 + (row & 7) + 1;
                #pragma unroll
                for (int nt = 0; nt < 3; nt++) {
                    const int col = nt * 8 + tig * 2;
                    if (col < 20) {
                        const float v0 = sB1[col], v1 = sB1[col + 1];
                        *(uint32_t*)&h1w[rc0 * 24 + col] =
                            pack_h2(fmaxf(acc1[mt][nt][0] + v0, 0.f),
                                    fmaxf(acc1[mt][nt][1] + v1, 0.f));
                        *(uint32_t*)&h1w[rc1 * 24 + col] =
                            pack_h2(fmaxf(acc1[mt][nt][2] + v0, 0.f),
                                    fmaxf(acc1[mt][nt][3] + v1, 0.f));
                    }
                }
            }
        }
        __syncthreads();

        // ---- conv2 ----
        {
            float acc[2][3][4];
            #pragma unroll
            for (int mt = 0; mt < 2; mt++)
                #pragma unroll
                for (int nt = 0; nt < 3; nt++)
                    #pragma unroll
                    for (int q = 0; q < 4; q++) acc[mt][nt][q] = 0.f;

            #pragma unroll
            for (int dy = 0; dy < 3; dy++) {
                const uint32_t ro = (uint32_t)dy * 480;
                const uint32_t wo = (uint32_t)dy * 3840;
                #pragma unroll
                for (int c = 0; c < 5; c++) {
                    const uint32_t ko = (uint32_t)c * 32;
                    uint32_t a0[4], a1[4], b01[4], bb2[2];
                    ldsm4(a0, aB0 + ro + ko);
                    ldsm4(a1, aB1 + ro + ko);
                    ldsm4(b01, bB01 + wo + ko);
                    ldsm2(bb2, bB2 + wo + ko);
                    mma_f16(acc[0][0], a0, b01[0], b01[1]);
                    mma_f16(acc[0][1], a0, b01[2], b01[3]);
                    mma_f16(acc[0][2], a0, bb2[0], bb2[1]);
                    mma_f16(acc[1][0], a1, b01[0], b01[1]);
                    mma_f16(acc[1][1], a1, b01[2], b01[3]);
                    mma_f16(acc[1][2], a1, bb2[0], bb2[1]);
                }
            }

            __half* dst = g_h2 + (size_t)(base_patch + iter * 4 + lp_w) * 1280;
            #pragma unroll
            for (int mt = 0; mt < 2; mt++) {
                const int row = hf * 32 + mt * 16 + g;
                #pragma unroll
                for (int nt = 0; nt < 3; nt++) {
                    const int col = nt * 8 + tig * 2;
                    if (col < 20) {
                        const float b0 = sB2[col], b1v = sB2[col + 1];
                        *(uint32_t*)&dst[row * 20 + col] =
                            pack_h2(fmaxf(acc[mt][nt][0] + b0, 0.f),
                                    fmaxf(acc[mt][nt][1] + b1v, 0.f));
                        *(uint32_t*)&dst[(row + 8) * 20 + col] =
                            pack_h2(fmaxf(acc[mt][nt][2] + b0, 0.f),
                                    fmaxf(acc[mt][nt][3] + b1v, 0.f));
                    }
                }
            }
        }
    }
}

// ===========================================================================
// Kernel 2: fused MLP, K=64 chunks, 2-buffer depth-1 cp.async pipeline.
// M=128, 512 threads. B/A chunk buffers stride 72 halves (conflict-free ldsm).
// ===========================================================================
#define ML_ACT  0                        // 128 x 264 halves = 67584
#define ML_B    67584                    // 2 x (256 x 72 halves) = 2 x 36864
#define ML_A    (67584 + 73728)          // 2 x (128 x 72 halves) = 2 x 18432
#define ML_SMEM (67584 + 73728 + 36864)  // 178176

__global__ __launch_bounds__(512, 1) void mlp_mma_kernel(
    const float* __restrict__ fc1_b, const float* __restrict__ fc2_b,
    const float* __restrict__ fc3_b, const float* __restrict__ fcf_b,
    float* __restrict__ out)
{
    extern __shared__ __align__(16) char smc[];
    __half* sAct = (__half*)(smc + ML_ACT);

    const int tid  = threadIdx.x;
    const int l    = tid & 31;
    const int wid  = tid >> 5;
    const int wm   = wid >> 2;
    const int wn   = wid & 3;
    const int g    = l >> 2;
    const int tig  = l & 3;
    const int m0   = blockIdx.x * 128;

    const uint32_t sActu = s2u(smc + ML_ACT);
    const uint32_t sBu   = s2u(smc + ML_B);
    const uint32_t sAu   = s2u(smc + ML_A);

    const int l16 = l & 15, lg = l >> 4;
    const uint32_t relA0 = (uint32_t)((wm * 32 + l16) * 72 + lg * 8) * 2;
    const uint32_t relA1 = relA0 + 16 * 72 * 2;
    const uint32_t cA0 = sActu + (uint32_t)((wm * 32 + l16) * 264 + lg * 8) * 2;
    const uint32_t cA1 = cA0 + 16 * 264 * 2;
    const int bt = l >> 3;
    const int bnl = (bt >> 1) * 8 + (l & 7);
    const int bkl = (bt & 1) * 8;
    uint32_t relB[4];
    #pragma unroll
    for (int gn = 0; gn < 4; gn++)
        relB[gn] = (uint32_t)((wn * 64 + gn * 16 + bnl) * 72 + bkl) * 2;

    // staging: B 256 rows, 2 threads/row x 64B; A 128 rows, 4 threads/row x 32B
    const int rB = tid >> 1, ofB = (tid & 1) * 32;
    const int rA = tid >> 2, qA = tid & 3;

    float acc[2][8][4];

    // ================= fc1: K=1280, 20 k64-chunks, A from g_h2 =================
    {
        #pragma unroll
        for (int mt = 0; mt < 2; mt++)
            #pragma unroll
            for (int nt = 0; nt < 8; nt++)
                #pragma unroll
                for (int q = 0; q < 4; q++) acc[mt][nt][q] = 0.f;

        auto issue1 = [&](int c) {
            const uint32_t bb = sBu + (uint32_t)(c & 1) * 36864;
            const uint32_t ab = sAu + (uint32_t)(c & 1) * 18432;
            const __half* bsrc = g_fc1h + (size_t)rB * 1280 + c * 64 + ofB;
            #pragma unroll
            for (int j = 0; j < 4; j++)
                cp16(bb + (uint32_t)(rB * 72 + ofB + j * 8) * 2, bsrc + j * 8);
            const __half* asrc = g_h2 + (size_t)(m0 + rA) * 1280 + c * 64 + qA * 16;
            cp16(ab + (uint32_t)(rA * 72 + qA * 16) * 2, asrc);
            cp16(ab + (uint32_t)(rA * 72 + qA * 16 + 8) * 2, asrc + 8);
            CP_COMMIT();
        };
        issue1(0);

        for (int c = 0; c < 20; c++) {
            CP_WAIT0();
            __syncthreads();
            if (c + 1 < 20) issue1(c + 1);
            const uint32_t bb = sBu + (uint32_t)(c & 1) * 36864;
            const uint32_t ab = sAu + (uint32_t)(c & 1) * 18432;
            #pragma unroll
            for (int kk = 0; kk < 64; kk += 16) {
                uint32_t a0[4], a1[4];
                ldsm4(a0, ab + relA0 + kk * 2);
                ldsm4(a1, ab + relA1 + kk * 2);
                #pragma unroll
                for (int gn = 0; gn < 4; gn++) {
                    uint32_t bbv[4];
                    ldsm4(bbv, bb + relB[gn] + kk * 2);
                    mma_f16(acc[0][2 * gn],     a0, bbv[0], bbv[1]);
                    mma_f16(acc[0][2 * gn + 1], a0, bbv[2], bbv[3]);
                    mma_f16(acc[1][2 * gn],     a1, bbv[0], bbv[1]);
                    mma_f16(acc[1][2 * gn + 1], a1, bbv[2], bbv[3]);
                }
            }
        }
        __syncthreads();
        #pragma unroll
        for (int mt = 0; mt < 2; mt++)
            #pragma unroll
            for (int nt = 0; nt < 8; nt++) {
                const int row = wm * 32 + mt * 16 + g;
                const int col = wn * 64 + nt * 8 + tig * 2;
                const float b0 = fc1_b[col], b1 = fc1_b[col + 1];
                *(uint32_t*)&sAct[row * 264 + col] =
                    pack_h2(fmaxf(acc[mt][nt][0] + b0, 0.f),
                            fmaxf(acc[mt][nt][1] + b1, 0.f));
                *(uint32_t*)&sAct[(row + 8) * 264 + col] =
                    pack_h2(fmaxf(acc[mt][nt][2] + b0, 0.f),
                            fmaxf(acc[mt][nt][3] + b1, 0.f));
            }
        __syncthreads();
    }

    // ================= fc2 & fc3: K=256, 4 k64-chunks =================
    for (int layer = 0; layer < 2; layer++) {
        const __half* wg = layer ? g_fc3h : g_fc2h;
        const float*  bg = layer ? fc3_b : fc2_b;
        #pragma unroll
        for (int mt = 0; mt < 2; mt++)
            #pragma unroll
            for (int nt = 0; nt < 8; nt++)
                #pragma unroll
                for (int q = 0; q < 4; q++) acc[mt][nt][q] = 0.f;

        auto issue2 = [&](int c) {
            const uint32_t bb = sBu + (uint32_t)(c & 1) * 36864;
            const __half* bsrc = wg + (size_t)rB * 256 + c * 64 + ofB;
            #pragma unroll
            for (int j = 0; j < 4; j++)
                cp16(bb + (uint32_t)(rB * 72 + ofB + j * 8) * 2, bsrc + j * 8);
            CP_COMMIT();
        };
        issue2(0);

        for (int c = 0; c < 4; c++) {
            CP_WAIT0();
            __syncthreads();
            if (c + 1 < 4) issue2(c + 1);
            const uint32_t bb = sBu + (uint32_t)(c & 1) * 36864;
            #pragma unroll
            for (int kk = 0; kk < 64; kk += 16) {
                const int kg = c * 64 + kk;
                uint32_t a0[4], a1[4];
                ldsm4(a0, cA0 + kg * 2);
                ldsm4(a1, cA1 + kg * 2);
                #pragma unroll
                for (int gn = 0; gn < 4; gn++) {
                    uint32_t bbv[4];
                    ldsm4(bbv, bb + relB[gn] + kk * 2);
                    mma_f16(acc[0][2 * gn],     a0, bbv[0], bbv[1]);
                    mma_f16(acc[0][2 * gn + 1], a0, bbv[2], bbv[3]);
                    mma_f16(acc[1][2 * gn],     a1, bbv[0], bbv[1]);
                    mma_f16(acc[1][2 * gn + 1], a1, bbv[2], bbv[3]);
                }
            }
        }
        __syncthreads();
        #pragma unroll
        for (int mt = 0; mt < 2; mt++)
            #pragma unroll
            for (int nt = 0; nt < 8; nt++) {
                const int row = wm * 32 + mt * 16 + g;
                const int col = wn * 64 + nt * 8 + tig * 2;
                const float b0 = bg[col], b1 = bg[col + 1];
                *(uint32_t*)&sAct[row * 264 + col] =
                    pack_h2(fmaxf(acc[mt][nt][0] + b0, 0.f),
                            fmaxf(acc[mt][nt][1] + b1, 0.f));
                *(uint32_t*)&sAct[(row + 8) * 264 + col] =
                    pack_h2(fmaxf(acc[mt][nt][2] + b0, 0.f),
                            fmaxf(acc[mt][nt][3] + b1, 0.f));
            }
        __syncthreads();
    }

    // ================= fcf: K=256, N=27 (pad 32) =================
    {
        __half* sB0 = (__half*)(smc + ML_B);
        for (int i = tid; i < 1056; i += 512)
            ((uint4*)sB0)[i] = ((const uint4*)g_fcfh)[i];
        __syncthreads();

        const int l2b = l & 15;
        const uint32_t bF = sBu +
            (uint32_t)((wn * 8 + (l2b & 7)) * 264 + ((l2b >> 3) & 1) * 8) * 2;

        float fa[2][4];
        #pragma unroll
        for (int mt = 0; mt < 2; mt++)
            #pragma unroll
            for (int q = 0; q < 4; q++) fa[mt][q] = 0.f;

        #pragma unroll 4
        for (int s = 0; s < 16; s++) {
            const int kg = s * 16;
            uint32_t a0[4], a1[4], bb[2];
            ldsm4(a0, cA0 + kg * 2);
            ldsm4(a1, cA1 + kg * 2);
            ldsm2(bb, bF + kg * 2);
            mma_f16(fa[0], a0, bb[0], bb[1]);
            mma_f16(fa[1], a1, bb[0], bb[1]);
        }

        #pragma unroll
        for (int mt = 0; mt < 2; mt++) {
            const int row = m0 + wm * 32 + mt * 16 + g;
            const int col = wn * 8 + tig * 2;
            #pragma unroll
            for (int h = 0; h < 2; h++) {
                const int rr = row + h * 8;
                if (rr < NP) {
                    if (col < 27)
                        out[(size_t)rr * 27 + col]     = fa[mt][h * 2 + 0] + fcf_b[col];
                    if (col + 1 < 27)
                        out[(size_t)rr * 27 + col + 1] = fa[mt][h * 2 + 1] + fcf_b[col + 1];
                }
            }
        }
    }
}

// ---------------------------------------------------------------------------
extern "C" void kernel_launch(void* const* d_in, const int* in_sizes, int n_in,
                              void* d_out, int out_size)
{
    const float* images  = (const float*)d_in[0];
    const float* conv1_w = (const float*)d_in[1];
    const float* conv1_b = (const float*)d_in[2];
    const float* conv2_w = (const float*)d_in[3];
    const float* conv2_b = (const float*)d_in[4];
    const float* fc1_w   = (const float*)d_in[5];
    const float* fc1_b   = (const float*)d_in[6];
    const float* fc2_w   = (const float*)d_in[7];
    const float* fc2_b   = (const float*)d_in[8];
    const float* fc3_w   = (const float*)d_in[9];
    const float* fc3_b   = (const float*)d_in[10];
    const float* fcf_w   = (const float*)d_in[11];
    const float* fcf_b   = (const float*)d_in[12];
    float* out = (float*)d_out;

    convert_kernel<<<1280, 256>>>(fc1_w, fc2_w, fc3_w, fcf_w, conv2_w, conv1_w);

    cudaFuncSetAttribute(conv_mma_kernel,
                         cudaFuncAttributeMaxDynamicSharedMemorySize, CV_SMEM);
    conv_mma_kernel<<<NP / (4 * NITER), 256, CV_SMEM>>>(images, conv1_b, conv2_b);

    cudaFuncSetAttribute(mlp_mma_kernel,
                         cudaFuncAttributeMaxDynamicSharedMemorySize, ML_SMEM);
    mlp_mma_kernel<<<MROWS_PAD / 128, 512, ML_SMEM>>>(
        fc1_b, fc2_b, fc3_b, fcf_b, out);
}